// round 4
// baseline (speedup 1.0000x reference)
#include <cuda_runtime.h>
#include <math.h>

#define BB 8
#define SS 64
#define NN 1024
#define CC 16
#define HH 128
#define PP 10
#define DT_STEP 7.0f
#define ROWS (BB*NN)                 // 8192
#define PRED_ELEMS (8388608L)        // B*S*N*C
#define FMAXV 3.402823466e38f

typedef unsigned long long ull;

// ---- scratch (__device__ globals; no cudaMalloc allowed) ----
__device__ float g_sol[PP*ROWS*HH];      // trajectory [P,B,N,H]; sol[p] = state after p steps
__device__ float g_u[ROWS*HH];           // silu(LN(s@w1+b1)) for current state
__device__ float g_logit[2*ROWS];        // double-buffered logits
__device__ float g_invdeg[NN];
__device__ int   g_deg[NN];
__device__ int   g_nbr[NN*NN];           // ordered neighbor lists
__device__ ull   g_w1p[64*HH];           // dyn_w1 packed: {w[2k][h], w[2k+1][h]}
__device__ ull   g_w2p[64*HH];           // dyn_w2 packed
__device__ ull   g_dw1p[64*HH];          // dec_w1 packed

__device__ __forceinline__ float nan2num(float v) {
    return isnan(v) ? 0.f : fminf(fmaxf(v, -FMAXV), FMAXV);
}

// ---- packed fp32x2 FMA (SASS FFMA2; ptxas never auto-emits, PTX-only) ----
__device__ __forceinline__ void fma2(ull& d, ull a, ull b) {
    asm("fma.rn.f32x2 %0, %1, %2, %0;" : "+l"(d) : "l"(a), "l"(b));
}
__device__ __forceinline__ float f2lo(ull v) { return __uint_as_float((unsigned)v); }
__device__ __forceinline__ float f2hi(ull v) { return __uint_as_float((unsigned)(v >> 32)); }

// ---- block-wide sums of R values (blockDim.x == 128) ----
template<int R>
__device__ __forceinline__ void bsumR(const float* v, float* out) {
    __shared__ float sh[4][R];
    int lane = threadIdx.x & 31, w = threadIdx.x >> 5;
    #pragma unroll
    for (int r = 0; r < R; r++) {
        float x = v[r];
        #pragma unroll
        for (int o = 16; o > 0; o >>= 1) x += __shfl_down_sync(0xffffffffu, x, o);
        if (lane == 0) sh[w][r] = x;
    }
    __syncthreads();
    #pragma unroll
    for (int r = 0; r < R; r++) out[r] = sh[0][r] + sh[1][r] + sh[2][r] + sh[3][r];
    __syncthreads();
}

__device__ __forceinline__ float bsum(float v) {
    __shared__ float sh[5];
    #pragma unroll
    for (int o = 16; o > 0; o >>= 1) v += __shfl_down_sync(0xffffffffu, v, o);
    if ((threadIdx.x & 31) == 0) sh[threadIdx.x >> 5] = v;
    __syncthreads();
    if (threadIdx.x == 0) sh[4] = sh[0] + sh[1] + sh[2] + sh[3];
    __syncthreads();
    float r = sh[4];
    __syncthreads();
    return r;
}

__device__ __forceinline__ float bmax(float v) {
    __shared__ float sh[5];
    #pragma unroll
    for (int o = 16; o > 0; o >>= 1) v = fmaxf(v, __shfl_down_sync(0xffffffffu, v, o));
    if ((threadIdx.x & 31) == 0) sh[threadIdx.x >> 5] = v;
    __syncthreads();
    if (threadIdx.x == 0) sh[4] = fmaxf(fmaxf(sh[0], sh[1]), fmaxf(sh[2], sh[3]));
    __syncthreads();
    float r = sh[4];
    __syncthreads();
    return r;
}

// ---- weight pre-pack: Wp[k2*128+h] = {W[2k2][h], W[2k2+1][h]} ----
__global__ void pack_kernel(const float* __restrict__ w1, const float* __restrict__ w2,
                            const float* __restrict__ dw1) {
    int i = blockIdx.x * 256 + threadIdx.x;    // 0 .. 8191
    int k2 = i >> 7, h = i & 127;
    float2 a;
    a.x = w1[(2*k2)*HH + h];  a.y = w1[(2*k2 + 1)*HH + h];  g_w1p[i]  = *(ull*)&a;
    a.x = w2[(2*k2)*HH + h];  a.y = w2[(2*k2 + 1)*HH + h];  g_w2p[i]  = *(ull*)&a;
    a.x = dw1[(2*k2)*HH + h]; a.y = dw1[(2*k2 + 1)*HH + h]; g_dw1p[i] = *(ull*)&a;
}

// ---- 8-row x 128-col GEMM via FFMA2: acc[r] = sum_k srow[r][k]*W[k][h] ----
__device__ __forceinline__ void gemm8_p(const ull* __restrict__ Wp, const float* srow,
                                        int h, float acc[8]) {
    ull ap[8];
    #pragma unroll
    for (int r = 0; r < 8; r++) ap[r] = 0ull;
    const ull* s2 = (const ull*)srow;          // [8][64] packed k-pairs (contiguous)
    #pragma unroll 8
    for (int k2 = 0; k2 < 64; k2++) {
        ull wp = Wp[k2*HH + h];                // LDG.64, L1-resident
        #pragma unroll
        for (int r = 0; r < 8; r++) fma2(ap[r], s2[r*64 + k2], wp);
    }
    #pragma unroll
    for (int r = 0; r < 8; r++) acc[r] = f2lo(ap[r]) + f2hi(ap[r]);
}

// ---- dyn1 tail: u = silu(LN(srow@w1+b1)); logit_out = srow@attn_w + attn_b ----
__device__ __forceinline__ void dyn1_tail(const float* srow, int row0, int h,
                                          const float* __restrict__ b1,
                                          const float* __restrict__ gn, const float* __restrict__ bt,
                                          const float* __restrict__ aw, const float* __restrict__ ab,
                                          float* __restrict__ logit_out) {
    float a[8];
    gemm8_p(g_w1p, srow, h, a);
    float bv = b1[h], gv = gn[h], btv = bt[h];
    #pragma unroll
    for (int r = 0; r < 8; r++) a[r] += bv;
    float mean[8];
    bsumR<8>(a, mean);
    float d[8], d2[8];
    #pragma unroll
    for (int r = 0; r < 8; r++) { d[r] = a[r] - mean[r]*(1.f/HH); d2[r] = d[r]*d[r]; }
    float var[8];
    bsumR<8>(d2, var);
    #pragma unroll
    for (int r = 0; r < 8; r++) {
        float z = d[r] * rsqrtf(var[r]*(1.f/HH) + 1e-5f) * gv + btv;
        g_u[(row0 + r)*HH + h] = z / (1.f + expf(-z));
    }
    float lv[8];
    float awv = aw[h];
    #pragma unroll
    for (int r = 0; r < 8; r++) lv[r] = srow[r*HH + h] * awv;
    float ls[8];
    bsumR<8>(lv, ls);
    if (h == 0) {
        float abv = ab[0];
        #pragma unroll
        for (int r = 0; r < 8; r++) logit_out[row0 + r] = ls[r] + abv;
    }
}

// ---- adjacency prep: deterministic ordered neighbor lists via ballot-prefix ----
__global__ void adjprep_kernel(const float* __restrict__ adj) {
    int m = blockIdx.x * 8 + (threadIdx.x >> 5);
    int lane = threadIdx.x & 31;
    int cnt = 0;
    for (int base = 0; base < NN; base += 32) {
        int n = base + lane;
        bool p = adj[m*NN + n] > 0.5f;
        unsigned bal = __ballot_sync(0xffffffffu, p);
        if (p) g_nbr[m*NN + cnt + __popc(bal & ((1u << lane) - 1u))] = n;
        cnt += __popc(bal);
    }
    if (lane == 0) {
        g_deg[m] = cnt;
        g_invdeg[m] = 1.f / ((float)cnt + 1e-8f);
    }
}

// ---- encoder fused with first dyn1 ----
__global__ void enc_dyn1_kernel(const float* __restrict__ x,
                                const float* __restrict__ ew, const float* __restrict__ eb,
                                const float* __restrict__ eg, const float* __restrict__ ebt,
                                const float* __restrict__ b1,
                                const float* __restrict__ gn, const float* __restrict__ bt,
                                const float* __restrict__ aw, const float* __restrict__ ab) {
    __shared__ __align__(16) float srow[8*HH];
    __shared__ float xr[8][CC];
    int h = threadIdx.x;
    int row0 = blockIdx.x * 8;
    {   // stage x[b, 0, n, :] for the 8 rows
        int r = h >> 4, c = h & 15;
        int row = row0 + r;
        int b = row / NN, n = row % NN;
        xr[r][c] = x[((long)(b*SS)*NN + n)*CC + c];
    }
    __syncthreads();
    float acc[8];
    float bv = eb[h];
    #pragma unroll
    for (int r = 0; r < 8; r++) {
        float a = bv;
        #pragma unroll
        for (int c = 0; c < CC; c++) a = fmaf(xr[r][c], ew[c*HH + h], a);
        acc[r] = a;
    }
    float mean[8];
    bsumR<8>(acc, mean);
    float d[8], d2[8];
    #pragma unroll
    for (int r = 0; r < 8; r++) { d[r] = acc[r] - mean[r]*(1.f/HH); d2[r] = d[r]*d[r]; }
    float var[8];
    bsumR<8>(d2, var);
    float gv = eg[h], btv = ebt[h];
    #pragma unroll
    for (int r = 0; r < 8; r++) {
        float y = d[r] * rsqrtf(var[r]*(1.f/HH) + 1e-5f) * gv + btv;
        float u = y / (1.f + expf(-y));
        g_sol[(row0 + r)*HH + h] = u;      // sol[0]
        srow[r*HH + h] = u;
    }
    __syncthreads();
    dyn1_tail(srow, row0, h, b1, gn, bt, aw, ab, &g_logit[0]);   // logits slot 0
}

// ---- fused ODE step: in-block softmax + dyn2 GEMM + sparse gather +
//      Euler update with norm clamp + (unless last) next step's dyn1 ----
__global__ void fused_step_kernel(const float* __restrict__ b2,
                                  const float* __restrict__ dsc, const float* __restrict__ tsc,
                                  const float* __restrict__ b1,
                                  const float* __restrict__ gn, const float* __restrict__ bt,
                                  const float* __restrict__ aw, const float* __restrict__ ab,
                                  int step, int last) {
    __shared__ __align__(16) float srow[8*HH];
    __shared__ float attn_s[NN];
    int h = threadIdx.x;
    int row0 = blockIdx.x * 8;
    int b = row0 / NN;                     // 8 consecutive rows share batch b
    int m0 = row0 % NN;

    // 0) softmax over nodes of batch b (block-local recompute)
    {
        const float* lg = &g_logit[(step & 1) * ROWS + b*NN];
        float lv[8];
        float m = -FMAXV;
        #pragma unroll
        for (int i = 0; i < 8; i++) { lv[i] = lg[i*HH + h]; m = fmaxf(m, lv[i]); }
        float M = bmax(m);
        float e[8];
        float s = 0.f;
        #pragma unroll
        for (int i = 0; i < 8; i++) { e[i] = expf(lv[i] - M); s += e[i]; }
        float S = bsum(s);
        float inv = 1.f / S;
        #pragma unroll
        for (int i = 0; i < 8; i++) attn_s[i*HH + h] = e[i] * inv;
    }

    // 1) dyn = tanh(u @ w2 + b2)
    #pragma unroll
    for (int r = 0; r < 8; r++) srow[r*HH + h] = g_u[(row0 + r)*HH + h];
    __syncthreads();                       // also covers attn_s writes
    float dyn[8];
    gemm8_p(g_w2p, srow, h, dyn);
    float bv = b2[h];
    #pragma unroll
    for (int r = 0; r < 8; r++) dyn[r] = tanhf(dyn[r] + bv);
    __syncthreads();                       // srow reused below

    // 2) diffusion gather on sol[step]
    const float* sb = &g_sol[(long)step*ROWS*HH + (long)b*NN*HH];
    float dscale = dsc[0], tscale = tsc[0];
    float dx[8];
    #pragma unroll
    for (int r = 0; r < 8; r++) {
        int m = m0 + r;
        int deg = g_deg[m];
        const int* nbr = &g_nbr[m*NN];
        float a0 = 0.f, a1 = 0.f;
        int j = 0;
        for (; j + 1 < deg; j += 2) {
            int n0 = __ldg(&nbr[j]), n1 = __ldg(&nbr[j + 1]);
            a0 = fmaf(attn_s[n0], sb[n0*HH + h], a0);
            a1 = fmaf(attn_s[n1], sb[n1*HH + h], a1);
        }
        if (j < deg) {
            int n0 = __ldg(&nbr[j]);
            a0 = fmaf(attn_s[n0], sb[n0*HH + h], a0);
        }
        float diff = (a0 + a1) * g_invdeg[m];
        dx[r] = tscale * (dyn[r] + diff * dscale);
    }

    // 3) norm clamp + Euler update into sol[step+1]
    float d2[8];
    #pragma unroll
    for (int r = 0; r < 8; r++) d2[r] = dx[r]*dx[r];
    float ss[8];
    bsumR<8>(d2, ss);
    float* snext = &g_sol[(long)(step + 1)*ROWS*HH];
    #pragma unroll
    for (int r = 0; r < 8; r++) {
        float nrm = sqrtf(ss[r]);
        float f = fminf(10.f / (nrm + 1e-8f), 1.f);
        float dxc = nan2num(dx[r] * f);
        float sv = sb[(long)(m0 + r)*HH + h] + dxc * DT_STEP;
        snext[(long)(row0 + r)*HH + h] = sv;
        srow[r*HH + h] = sv;
    }
    __syncthreads();

    // 4) next step's dyn1 (writes u + logits for step+1 into the other slot)
    if (!last) dyn1_tail(srow, row0, h, b1, gn, bt, aw, ab,
                         &g_logit[((step + 1) & 1) * ROWS]);
}

// ---- decode: one block per (b,n); fuses solW GEMM, lerp, LN, SiLU, pred GEMM ----
__global__ void decode_kernel(const float* __restrict__ b1,
                              const float* __restrict__ dg, const float* __restrict__ dbt,
                              const float* __restrict__ w2, const float* __restrict__ b2,
                              float* __restrict__ out) {
    __shared__ __align__(16) float sol_s[PP*HH];     // 10 x 128
    __shared__ __align__(16) float solW_s[PP*HH];    // 10 x 128
    __shared__ __align__(16) float w2T[CC*132];      // transposed dec_w2, pitch 132
    __shared__ __align__(16) float hsm[4][HH];       // per-warp silu buffer
    int h = threadIdx.x;
    int rem = blockIdx.x;                  // b*NN + n
    int b = rem / NN, n = rem % NN;

    #pragma unroll
    for (int p = 0; p < PP; p++)
        sol_s[p*HH + h] = g_sol[(long)p*ROWS*HH + (long)rem*HH + h];
    #pragma unroll
    for (int c = 0; c < CC; c++)
        w2T[c*132 + h] = w2[h*CC + c];
    __syncthreads();

    // solW = sol @ dec_w1 + dec_b1 (10 rows), FFMA2
    {
        ull ap[PP];
        #pragma unroll
        for (int p = 0; p < PP; p++) ap[p] = 0ull;
        const ull* s2 = (const ull*)sol_s;           // [10][64]
        #pragma unroll 4
        for (int k2 = 0; k2 < 64; k2++) {
            ull wp = g_dw1p[k2*HH + h];
            #pragma unroll
            for (int p = 0; p < PP; p++) fma2(ap[p], s2[p*64 + k2], wp);
        }
        float bv = b1[h];
        #pragma unroll
        for (int p = 0; p < PP; p++) solW_s[p*HH + h] = f2lo(ap[p]) + f2hi(ap[p]) + bv;
    }
    __syncthreads();

    // warp w handles s = w*16 .. w*16+15; lane l owns h = 4l..4l+3
    int w = h >> 5, l = h & 31;
    int c = l & 15, half = l >> 4;
    const float4* sol4  = (const float4*)sol_s;      // [10][32]
    const float4* solW4 = (const float4*)solW_s;
    float4 g4  = *(const float4*)&dg[4*l];
    float4 bt4 = *(const float4*)&dbt[4*l];
    float bias = (l < CC) ? b2[l] : 0.f;

    for (int si = 0; si < 16; si++) {
        int s = w*16 + si;
        int ic = (s + 6) / 7;              // searchsorted(t, s, 'left') + clip
        if (ic < 1) ic = 1;
        if (ic > PP - 1) ic = PP - 1;
        float alpha = (float)(s - 7*(ic - 1)) * (1.f/7.f);
        float oma = 1.f - alpha;

        float4 y0 = solW4[(ic - 1)*32 + l];
        float4 y1 = solW4[ic*32 + l];
        float yx = oma*y0.x + alpha*y1.x;
        float yy = oma*y0.y + alpha*y1.y;
        float yz = oma*y0.z + alpha*y1.z;
        float yw = oma*y0.w + alpha*y1.w;

        float sum = yx + yy + yz + yw;
        #pragma unroll
        for (int o = 16; o > 0; o >>= 1) sum += __shfl_xor_sync(0xffffffffu, sum, o);
        float mean = sum * (1.f/HH);
        float dxv = yx - mean, dyv = yy - mean, dzv = yz - mean, dwv = yw - mean;
        float ssum = dxv*dxv + dyv*dyv + dzv*dzv + dwv*dwv;
        #pragma unroll
        for (int o = 16; o > 0; o >>= 1) ssum += __shfl_xor_sync(0xffffffffu, ssum, o);
        float rs = rsqrtf(ssum*(1.f/HH) + 1e-5f);

        float zx = dxv*rs*g4.x + bt4.x;
        float zy = dyv*rs*g4.y + bt4.y;
        float zz = dzv*rs*g4.z + bt4.z;
        float zw = dwv*rs*g4.w + bt4.w;
        float4 hv;
        hv.x = zx / (1.f + expf(-zx));
        hv.y = zy / (1.f + expf(-zy));
        hv.z = zz / (1.f + expf(-zz));
        hv.w = zw / (1.f + expf(-zw));
        *(float4*)&hsm[w][4*l] = hv;

        float4 s0 = sol4[(ic - 1)*32 + l];
        float4 s1 = sol4[ic*32 + l];
        float4 itp;
        itp.x = oma*s0.x + alpha*s1.x;
        itp.y = oma*s0.y + alpha*s1.y;
        itp.z = oma*s0.z + alpha*s1.z;
        itp.w = oma*s0.w + alpha*s1.w;
        *(float4*)&out[PRED_ELEMS + ((long)s*BB*NN + rem)*HH + 4*l] = itp;

        __syncwarp();

        // pred[c] = sum_h hsm[h]*w2T[c][h] via FFMA2 (both operands contiguous)
        const ull* h2 = (const ull*)&hsm[w][half*64];
        const ull* v2 = (const ull*)&w2T[c*132 + half*64];
        ull accp = 0ull;
        #pragma unroll
        for (int j = 0; j < 32; j++) fma2(accp, h2[j], v2[j]);
        float acc = f2lo(accp) + f2hi(accp);
        acc += __shfl_xor_sync(0xffffffffu, acc, 16);
        if (l < CC)
            out[(((long)b*SS + s)*NN + n)*CC + l] = acc + bias;
        __syncwarp();
    }
}

extern "C" void kernel_launch(void* const* d_in, const int* in_sizes, int n_in,
                              void* d_out, int out_size) {
    const float* x        = (const float*)d_in[0];
    const float* adj      = (const float*)d_in[1];
    const float* enc_w    = (const float*)d_in[2];
    const float* enc_b    = (const float*)d_in[3];
    const float* enc_g    = (const float*)d_in[4];
    const float* enc_beta = (const float*)d_in[5];
    const float* dyn_w1   = (const float*)d_in[6];
    const float* dyn_b1   = (const float*)d_in[7];
    const float* dyn_g    = (const float*)d_in[8];
    const float* dyn_beta = (const float*)d_in[9];
    const float* dyn_w2   = (const float*)d_in[10];
    const float* dyn_b2   = (const float*)d_in[11];
    const float* attn_w   = (const float*)d_in[12];
    const float* attn_b   = (const float*)d_in[13];
    const float* dsc      = (const float*)d_in[14];
    const float* tsc      = (const float*)d_in[15];
    const float* dec_w1   = (const float*)d_in[16];
    const float* dec_b1   = (const float*)d_in[17];
    const float* dec_g    = (const float*)d_in[18];
    const float* dec_beta = (const float*)d_in[19];
    const float* dec_w2   = (const float*)d_in[20];
    const float* dec_b2   = (const float*)d_in[21];
    float* out = (float*)d_out;

    pack_kernel<<<32, 256>>>(dyn_w1, dyn_w2, dec_w1);
    adjprep_kernel<<<NN/8, 256>>>(adj);
    enc_dyn1_kernel<<<ROWS/8, HH>>>(x, enc_w, enc_b, enc_g, enc_beta,
                                    dyn_b1, dyn_g, dyn_beta, attn_w, attn_b);

    for (int step = 0; step < PP - 1; step++) {
        fused_step_kernel<<<ROWS/8, HH>>>(dyn_b2, dsc, tsc,
                                          dyn_b1, dyn_g, dyn_beta,
                                          attn_w, attn_b, step, step == PP - 2);
    }

    decode_kernel<<<ROWS, HH>>>(dec_b1, dec_g, dec_beta, dec_w2, dec_b2, out);
}